// round 3
// baseline (speedup 1.0000x reference)
#include <cuda_runtime.h>
#include <cuda_bf16.h>
#include <math.h>

// Problem constants (fixed shapes)
#define NN 4096
#define DD 256
#define HH 8
#define DH 32
#define NW 128          // adjacency words per row (4096/32)
#define MAXD 512        // max neighbors kept (avg ~64 for random E=131072 graph)

// -------- static device scratch (no allocations allowed; referenced ONLY from device code) --------
__device__ unsigned g_adj[NN * NW];        // 2 MB bitmask adjacency
__device__ int      g_deg[NN];
__device__ int      g_nbr[NN * MAXD];      // 8 MB compact neighbor lists
__device__ float    g_qkv[NN * 3 * DD];    // 12 MB
__device__ float    g_ctx[NN * DD];        // 4 MB
__device__ float    g_x  [NN * DD];        // 4 MB  (after out-proj + select)
__device__ float    g_y  [NN * DD];        // 4 MB  (after lin, pre-LN)

// -------- zero the adjacency bitmask --------
__global__ void zero_adj_kernel() {
    int i = blockIdx.x * blockDim.x + threadIdx.x;
    if (i < NN * NW) g_adj[i] = 0u;
}

// -------- scatter edges into bitmask (symmetric, no self loops, dedup via OR) --------
// edge_index is int32 (JAX default x64-disabled downcasts int64 -> int32).
__global__ void build_adj_kernel(const int* __restrict__ ei, int ne) {
    int e = blockIdx.x * blockDim.x + threadIdx.x;
    if (e >= ne) return;
    int s = ei[e];
    int d = ei[ne + e];
    if (s == d) return;
    if ((unsigned)s >= NN || (unsigned)d >= NN) return;  // safety: never trap
    atomicOr(&g_adj[s * NW + (d >> 5)], 1u << (d & 31));
    atomicOr(&g_adj[d * NW + (s >> 5)], 1u << (s & 31));
}

// -------- compact bitmask rows to neighbor lists + degree --------
__global__ void compact_kernel() {
    __shared__ int cnt;
    int n = blockIdx.x;
    if (threadIdx.x == 0) cnt = 0;
    __syncthreads();
    unsigned bits = g_adj[n * NW + threadIdx.x];
    int c = __popc(bits);
    int base = 0;
    if (c) base = atomicAdd(&cnt, c);
    while (bits) {
        int b = __ffs(bits) - 1;
        bits &= bits - 1;
        if (base < MAXD) g_nbr[n * MAXD + base] = threadIdx.x * 32 + b;
        base++;
    }
    __syncthreads();
    if (threadIdx.x == 0) g_deg[n] = (cnt < MAXD) ? cnt : MAXD;
}

// -------- tiled fp32 GEMM:  C[M,Nc] = A[M,K] @ B[Nc,K]^T + bias  (both K-contiguous) --------
// ASEL: 0 = emb (arg), 1 = g_ctx, 2 = g_x
// CSEL: 0 = g_qkv, 1 = g_x, 2 = g_y
// SELECT: rows with deg==0 take emb[row,col] instead (out-proj epilogue).
#define BM 64
#define BN 64
#define BK 16

template<int ASEL, int CSEL, bool SELECT>
__global__ void gemm_nt_kernel(const float* __restrict__ emb, const float* __restrict__ B,
                               const float* __restrict__ bias, int Nc, int K) {
    const float* A = (ASEL == 0) ? emb : (ASEL == 1 ? (const float*)g_ctx : (const float*)g_x);
    float*       C = (CSEL == 0) ? g_qkv : (CSEL == 1 ? g_x : g_y);

    __shared__ float As[BK][BM + 4];
    __shared__ float Bs[BK][BN + 4];
    const int tid = threadIdx.x;
    const int tx = tid & 15;
    const int ty = tid >> 4;
    const int row0 = blockIdx.y * BM;
    const int col0 = blockIdx.x * BN;

    float acc[4][4] = {};

    const int lr = tid >> 2;         // 0..63
    const int lc = (tid & 3) * 4;    // 0,4,8,12
    const float* Ap = A + (size_t)(row0 + lr) * K + lc;
    const float* Bp = B + (size_t)(col0 + lr) * K + lc;

    for (int k0 = 0; k0 < K; k0 += BK) {
        float4 av = *(const float4*)(Ap + k0);
        float4 bv = *(const float4*)(Bp + k0);
        As[lc + 0][lr] = av.x; As[lc + 1][lr] = av.y;
        As[lc + 2][lr] = av.z; As[lc + 3][lr] = av.w;
        Bs[lc + 0][lr] = bv.x; Bs[lc + 1][lr] = bv.y;
        Bs[lc + 2][lr] = bv.z; Bs[lc + 3][lr] = bv.w;
        __syncthreads();
#pragma unroll
        for (int kk = 0; kk < BK; kk++) {
            float4 a = *(const float4*)&As[kk][ty * 4];
            float4 b = *(const float4*)&Bs[kk][tx * 4];
            float ar[4] = {a.x, a.y, a.z, a.w};
            float br[4] = {b.x, b.y, b.z, b.w};
#pragma unroll
            for (int i = 0; i < 4; i++)
#pragma unroll
                for (int j = 0; j < 4; j++)
                    acc[i][j] += ar[i] * br[j];
        }
        __syncthreads();
    }

#pragma unroll
    for (int i = 0; i < 4; i++) {
        int r = row0 + ty * 4 + i;
        bool take_alt = SELECT && (g_deg[r] == 0);
#pragma unroll
        for (int j = 0; j < 4; j++) {
            int c = col0 + tx * 4 + j;
            float v = acc[i][j] + bias[c];
            if (SELECT && take_alt) v = emb[(size_t)r * DD + c];
            C[(size_t)r * Nc + c] = v;
        }
    }
}

// -------- sparse attention: warp per (node, head), online softmax over neighbors --------
__global__ void attn_kernel() {
    int n = blockIdx.x;
    int tid = threadIdx.x;            // tid = head*32 + lane
    int dg = g_deg[n];

    float q = g_qkv[(size_t)n * 768 + tid];   // q part occupies [0,256)
    float m = -1e30f, s = 0.f, acc = 0.f;
    const int* nl = g_nbr + (size_t)n * MAXD;

    for (int i = 0; i < dg; i++) {
        int nb = nl[i];
        const float* kvp = g_qkv + (size_t)nb * 768 + 256 + tid;  // k at +256, v at +512
        float p = q * kvp[0];
#pragma unroll
        for (int o = 16; o; o >>= 1) p += __shfl_xor_sync(0xffffffffu, p, o);
        p *= 0.17677669529663687f;    // 1/sqrt(32)
        float nm = fmaxf(m, p);
        float f = __expf(m - nm);
        float e = __expf(p - nm);
        s = s * f + e;
        acc = acc * f + e * kvp[256];
        m = nm;
    }
    g_ctx[(size_t)n * DD + tid] = dg ? (acc / s) : 0.f;
}

// -------- fused LayerNorm + exact GELU --------
__global__ void ln_gelu_kernel(const float* __restrict__ g, const float* __restrict__ beta,
                               float* __restrict__ out) {
    __shared__ float red1[8];
    __shared__ float red2[8];
    int r = blockIdx.x;
    int t = threadIdx.x;
    float v = g_y[(size_t)r * DD + t];

    float x = v;
    float x2 = v * v;
#pragma unroll
    for (int o = 16; o; o >>= 1) {
        x  += __shfl_xor_sync(0xffffffffu, x, o);
        x2 += __shfl_xor_sync(0xffffffffu, x2, o);
    }
    if ((t & 31) == 0) { red1[t >> 5] = x; red2[t >> 5] = x2; }
    __syncthreads();
    float sum = 0.f, ss = 0.f;
#pragma unroll
    for (int i = 0; i < 8; i++) { sum += red1[i]; ss += red2[i]; }
    float mean = sum * (1.f / 256.f);
    float var  = ss * (1.f / 256.f) - mean * mean;

    float yv = (v - mean) * rsqrtf(var + 1e-5f) * g[t] + beta[t];
    out[(size_t)r * DD + t] = 0.5f * yv * (1.f + erff(yv * 0.70710678118654752f));
}

// ------------------------------------------------------------------
extern "C" void kernel_launch(void* const* d_in, const int* in_sizes, int n_in,
                              void* d_out, int out_size) {
    const float* emb   = (const float*)d_in[0];
    const int*   ei    = (const int*)d_in[1];     // int32 (JAX default)
    const float* w_in  = (const float*)d_in[2];
    const float* b_in  = (const float*)d_in[3];
    const float* w_out = (const float*)d_in[4];
    const float* b_out = (const float*)d_in[5];
    const float* w_lin = (const float*)d_in[6];
    const float* b_lin = (const float*)d_in[7];
    const float* ln_g  = (const float*)d_in[8];
    const float* ln_b  = (const float*)d_in[9];
    float* out = (float*)d_out;

    const int ne = in_sizes[1] / 2;               // number of edges

    // 1. adjacency
    zero_adj_kernel<<<(NN * NW + 255) / 256, 256>>>();
    build_adj_kernel<<<(ne + 255) / 256, 256>>>(ei, ne);
    compact_kernel<<<NN, NW>>>();

    // 2. qkv = emb @ W_in^T + b_in   [4096, 768]
    gemm_nt_kernel<0, 0, false><<<dim3(768 / BN, NN / BM), 256>>>(emb, w_in, b_in, 768, DD);

    // 3. sparse masked attention -> ctx [4096, 256]
    attn_kernel<<<NN, 256>>>();

    // 4. x = has_nb ? ctx @ W_out^T + b_out : emb
    gemm_nt_kernel<1, 1, true><<<dim3(DD / BN, NN / BM), 256>>>(emb, w_out, b_out, DD, DD);

    // 5. y = x @ W_lin^T + b_lin
    gemm_nt_kernel<2, 2, false><<<dim3(DD / BN, NN / BM), 256>>>(emb, w_lin, b_lin, DD, DD);

    // 6. LayerNorm + exact GELU -> out
    ln_gelu_kernel<<<NN, 256>>>(ln_g, ln_b, out);
}

// round 4
// speedup vs baseline: 1.0290x; 1.0290x over previous
#include <cuda_runtime.h>
#include <cuda_bf16.h>
#include <math.h>

// Problem constants (fixed shapes)
#define NN 4096
#define DD 256
#define NW 128          // adjacency words per row (4096/32)
#define MAXD 512        // max neighbors kept (avg ~64 for random E=131072 graph)
#define BK 8

// -------- static device scratch --------
__device__ unsigned g_adj[NN * NW];        // 2 MB bitmask adjacency
__device__ int      g_deg[NN];
__device__ int      g_nbr[NN * MAXD];      // 8 MB compact neighbor lists (sorted)
__device__ float    g_qkv[NN * 3 * DD];    // 12 MB
__device__ float    g_ctx[NN * DD];        // 4 MB
__device__ float    g_x  [NN * DD];        // 4 MB
__device__ float    g_y  [NN * DD];        // 4 MB

// -------- zero the adjacency bitmask --------
__global__ void zero_adj_kernel() {
    int i = blockIdx.x * blockDim.x + threadIdx.x;
    if (i < NN * NW) g_adj[i] = 0u;
}

// -------- scatter edges (symmetric, no self loops, dedup via OR); edge_index is int32 --------
__global__ void build_adj_kernel(const int* __restrict__ ei, int ne) {
    int e = blockIdx.x * blockDim.x + threadIdx.x;
    if (e >= ne) return;
    int s = ei[e];
    int d = ei[ne + e];
    if (s == d) return;
    if ((unsigned)s >= NN || (unsigned)d >= NN) return;
    atomicOr(&g_adj[s * NW + (d >> 5)], 1u << (d & 31));
    atomicOr(&g_adj[d * NW + (s >> 5)], 1u << (s & 31));
}

// -------- deterministic compaction: block prefix-scan, sorted neighbor lists --------
__global__ void compact_kernel() {
    __shared__ int wsum[4];
    int n = blockIdx.x, t = threadIdx.x;
    unsigned bits = g_adj[n * NW + t];
    int c = __popc(bits);
    int lane = t & 31, w = t >> 5;
    int x = c;
#pragma unroll
    for (int o = 1; o < 32; o <<= 1) {
        int y = __shfl_up_sync(0xffffffffu, x, o);
        if (lane >= o) x += y;
    }
    if (lane == 31) wsum[w] = x;
    __syncthreads();
    int woff = 0;
#pragma unroll
    for (int i = 0; i < 4; i++) if (i < w) woff += wsum[i];
    int base = woff + x - c;                // exclusive prefix
    int total = wsum[0] + wsum[1] + wsum[2] + wsum[3];
    while (bits) {
        int b = __ffs(bits) - 1;
        bits &= bits - 1;
        if (base < MAXD) g_nbr[n * MAXD + base] = t * 32 + b;
        base++;
    }
    if (t == 0) g_deg[n] = (total < MAXD) ? total : MAXD;
}

// -------- tiled fp32 GEMM: C[M,Nc] = A[M,K] @ B[Nc,K]^T + bias --------
// BM=128, BN=64, TM=TN=8, 128 threads, BK=8, double-buffered smem.
// ASEL: 0 = emb, 1 = g_ctx, 2 = g_x;  CSEL: 0 = g_qkv, 1 = g_x, 2 = g_y
// SELECT: rows with deg==0 take emb[row,col] (out-proj epilogue)
#define BM 128
#define BN 64
#define TM 8
#define TN 8
#define NT ((BM / TM) * (BN / TN))   // 128 threads

template<int ASEL, int CSEL, bool SELECT>
__global__ __launch_bounds__(NT) void gemm_kernel(const float* __restrict__ emb,
                                                  const float* __restrict__ B,
                                                  const float* __restrict__ bias,
                                                  int Nc, int K) {
    const float* A = (ASEL == 0) ? emb : (ASEL == 1 ? (const float*)g_ctx : (const float*)g_x);
    float*       C = (CSEL == 0) ? g_qkv : (CSEL == 1 ? g_x : g_y);

    __shared__ float As[2][BK][BM];   // 8 KB
    __shared__ float Bs[2][BK][BN];   // 4 KB

    const int tid = threadIdx.x;
    const int row0 = blockIdx.y * BM;
    const int col0 = blockIdx.x * BN;
    const int tx = tid % (BN / TN);   // 0..7
    const int ty = tid / (BN / TN);   // 0..15

    constexpr int AF4 = BM * BK / 4;  // 256 float4 per A tile
    constexpr int BF4 = BN * BK / 4;  // 128 float4 per B tile
    constexpr int ALD = AF4 / NT;     // 2
    constexpr int BLD = BF4 / NT;     // 1

    float4 ra[ALD], rb[BLD];
    float acc[TM][TN] = {};

    auto gload = [&](int k0) {
#pragma unroll
        for (int u = 0; u < ALD; u++) {
            int i = tid + u * NT;
            int r = i >> 1, kk = (i & 1) * 4;
            ra[u] = *(const float4*)(A + (size_t)(row0 + r) * K + k0 + kk);
        }
#pragma unroll
        for (int u = 0; u < BLD; u++) {
            int i = tid + u * NT;
            int r = i >> 1, kk = (i & 1) * 4;
            rb[u] = *(const float4*)(B + (size_t)(col0 + r) * K + k0 + kk);
        }
    };
    auto sstore = [&](int buf) {
#pragma unroll
        for (int u = 0; u < ALD; u++) {
            int i = tid + u * NT;
            int r = i >> 1, kk = (i & 1) * 4;
            As[buf][kk + 0][r] = ra[u].x;
            As[buf][kk + 1][r] = ra[u].y;
            As[buf][kk + 2][r] = ra[u].z;
            As[buf][kk + 3][r] = ra[u].w;
        }
#pragma unroll
        for (int u = 0; u < BLD; u++) {
            int i = tid + u * NT;
            int r = i >> 1, kk = (i & 1) * 4;
            Bs[buf][kk + 0][r] = rb[u].x;
            Bs[buf][kk + 1][r] = rb[u].y;
            Bs[buf][kk + 2][r] = rb[u].z;
            Bs[buf][kk + 3][r] = rb[u].w;
        }
    };

    gload(0);
    sstore(0);
    __syncthreads();

    const int KT = K / BK;
    for (int kt = 0; kt < KT; kt++) {
        int buf = kt & 1;
        if (kt + 1 < KT) gload((kt + 1) * BK);
#pragma unroll
        for (int kk = 0; kk < BK; kk++) {
            float a[TM], b[TN];
#pragma unroll
            for (int u = 0; u < TM; u += 4)
                *(float4*)&a[u] = *(const float4*)&As[buf][kk][ty * TM + u];
#pragma unroll
            for (int u = 0; u < TN; u += 4)
                *(float4*)&b[u] = *(const float4*)&Bs[buf][kk][tx * TN + u];
#pragma unroll
            for (int i = 0; i < TM; i++)
#pragma unroll
                for (int j = 0; j < TN; j++)
                    acc[i][j] += a[i] * b[j];
        }
        if (kt + 1 < KT) {
            sstore(buf ^ 1);
            __syncthreads();
        }
    }

    // epilogue (vectorized stores)
#pragma unroll
    for (int i = 0; i < TM; i++) {
        int r = row0 + ty * TM + i;
        bool alt = SELECT && (g_deg[r] == 0);
#pragma unroll
        for (int j = 0; j < TN; j += 4) {
            int cc = col0 + tx * TN + j;
            float4 bv = *(const float4*)(bias + cc);
            float4 v;
            v.x = acc[i][j + 0] + bv.x;
            v.y = acc[i][j + 1] + bv.y;
            v.z = acc[i][j + 2] + bv.z;
            v.w = acc[i][j + 3] + bv.w;
            if (SELECT && alt) v = *(const float4*)(emb + (size_t)r * DD + cc);
            *(float4*)(C + (size_t)r * Nc + cc) = v;
        }
    }
}

// -------- sparse attention: warp per (node, head), online softmax, 4-way unrolled --------
__global__ void attn_kernel() {
    __shared__ int snbr[MAXD];
    __shared__ int sdeg;
    int n = blockIdx.x, tid = threadIdx.x;
    if (tid == 0) sdeg = g_deg[n];
    __syncthreads();
    int dg = sdeg;
    for (int i = tid; i < dg; i += 256) snbr[i] = g_nbr[(size_t)n * MAXD + i];
    __syncthreads();
    if (dg == 0) {
        g_ctx[(size_t)n * DD + tid] = 0.f;
        return;
    }

    float q = g_qkv[(size_t)n * 768 + tid];   // q occupies [0,256); tid = head*32+lane
    float m = -1e30f, s = 0.f, acc = 0.f;
    const float sc = 0.17677669529663687f;    // 1/sqrt(32)

    for (int i = 0; i < dg; i += 4) {
        int i1 = min(i + 1, dg - 1), i2 = min(i + 2, dg - 1), i3 = min(i + 3, dg - 1);
        const float* b0 = g_qkv + (size_t)snbr[i]  * 768 + 256 + tid;
        const float* b1 = g_qkv + (size_t)snbr[i1] * 768 + 256 + tid;
        const float* b2 = g_qkv + (size_t)snbr[i2] * 768 + 256 + tid;
        const float* b3 = g_qkv + (size_t)snbr[i3] * 768 + 256 + tid;
        float k0 = b0[0], k1 = b1[0], k2 = b2[0], k3 = b3[0];
        float v0 = b0[256], v1 = b1[256], v2 = b2[256], v3 = b3[256];

        float p0 = q * k0, p1 = q * k1, p2 = q * k2, p3 = q * k3;
#pragma unroll
        for (int o = 16; o; o >>= 1) {
            p0 += __shfl_xor_sync(0xffffffffu, p0, o);
            p1 += __shfl_xor_sync(0xffffffffu, p1, o);
            p2 += __shfl_xor_sync(0xffffffffu, p2, o);
            p3 += __shfl_xor_sync(0xffffffffu, p3, o);
        }
        p0 *= sc; p1 *= sc; p2 *= sc; p3 *= sc;
        if (i + 1 >= dg) p1 = -1e30f;
        if (i + 2 >= dg) p2 = -1e30f;
        if (i + 3 >= dg) p3 = -1e30f;

        float mx = fmaxf(fmaxf(fmaxf(p0, p1), fmaxf(p2, p3)), m);
        float f  = __expf(m - mx);
        float e0 = __expf(p0 - mx), e1 = __expf(p1 - mx);
        float e2 = __expf(p2 - mx), e3 = __expf(p3 - mx);
        s   = s * f + e0 + e1 + e2 + e3;
        acc = acc * f + e0 * v0 + e1 * v1 + e2 * v2 + e3 * v3;
        m = mx;
    }
    g_ctx[(size_t)n * DD + tid] = acc / s;
}

// -------- fused LayerNorm + exact GELU --------
__global__ void ln_gelu_kernel(const float* __restrict__ g, const float* __restrict__ beta,
                               float* __restrict__ out) {
    __shared__ float red1[8];
    __shared__ float red2[8];
    int r = blockIdx.x;
    int t = threadIdx.x;
    float v = g_y[(size_t)r * DD + t];

    float x = v, x2 = v * v;
#pragma unroll
    for (int o = 16; o; o >>= 1) {
        x  += __shfl_xor_sync(0xffffffffu, x, o);
        x2 += __shfl_xor_sync(0xffffffffu, x2, o);
    }
    if ((t & 31) == 0) { red1[t >> 5] = x; red2[t >> 5] = x2; }
    __syncthreads();
    float sum = 0.f, ss = 0.f;
#pragma unroll
    for (int i = 0; i < 8; i++) { sum += red1[i]; ss += red2[i]; }
    float mean = sum * (1.f / 256.f);
    float var  = ss * (1.f / 256.f) - mean * mean;

    float yv = (v - mean) * rsqrtf(var + 1e-5f) * g[t] + beta[t];
    out[(size_t)r * DD + t] = 0.5f * yv * (1.f + erff(yv * 0.70710678118654752f));
}

// ------------------------------------------------------------------
extern "C" void kernel_launch(void* const* d_in, const int* in_sizes, int n_in,
                              void* d_out, int out_size) {
    const float* emb   = (const float*)d_in[0];
    const int*   ei    = (const int*)d_in[1];     // int32 (JAX default)
    const float* w_in  = (const float*)d_in[2];
    const float* b_in  = (const float*)d_in[3];
    const float* w_out = (const float*)d_in[4];
    const float* b_out = (const float*)d_in[5];
    const float* w_lin = (const float*)d_in[6];
    const float* b_lin = (const float*)d_in[7];
    const float* ln_g  = (const float*)d_in[8];
    const float* ln_b  = (const float*)d_in[9];
    float* out = (float*)d_out;

    const int ne = in_sizes[1] / 2;

    // 1. adjacency
    zero_adj_kernel<<<(NN * NW + 255) / 256, 256>>>();
    build_adj_kernel<<<(ne + 255) / 256, 256>>>(ei, ne);
    compact_kernel<<<NN, NW>>>();

    // 2. qkv = emb @ W_in^T + b_in   [4096, 768]
    gemm_kernel<0, 0, false><<<dim3(768 / BN, NN / BM), NT>>>(emb, w_in, b_in, 768, DD);

    // 3. sparse masked attention -> ctx [4096, 256]
    attn_kernel<<<NN, 256>>>();

    // 4. x = has_nb ? ctx @ W_out^T + b_out : emb
    gemm_kernel<1, 1, true><<<dim3(DD / BN, NN / BM), NT>>>(emb, w_out, b_out, DD, DD);

    // 5. y = x @ W_lin^T + b_lin
    gemm_kernel<2, 2, false><<<dim3(DD / BN, NN / BM), NT>>>(emb, w_lin, b_lin, DD, DD);

    // 6. LayerNorm + exact GELU -> out
    ln_gelu_kernel<<<NN, 256>>>(ln_g, ln_b, out);
}

// round 5
// speedup vs baseline: 1.2254x; 1.1909x over previous
#include <cuda_runtime.h>
#include <cuda_bf16.h>
#include <mma.h>
#include <math.h>

using namespace nvcuda;

// Problem constants (fixed shapes)
#define NN 4096
#define DD 256
#define NW 128          // adjacency words per row (4096/32)
#define MAXD 512        // max neighbors kept (avg ~64 for random E=131072 graph)

// -------- static device scratch --------
__device__ unsigned g_adj[NN * NW];        // 2 MB bitmask adjacency
__device__ int      g_deg[NN];
__device__ int      g_nbr[NN * MAXD];      // 8 MB compact neighbor lists (sorted)
__device__ float    g_qkv[NN * 3 * DD];    // 12 MB
__device__ float    g_ctx[NN * DD];        // 4 MB
__device__ float    g_x  [NN * DD];        // 4 MB
__device__ float    g_y  [NN * DD];        // 4 MB

// -------- zero the adjacency bitmask --------
__global__ void zero_adj_kernel() {
    int i = blockIdx.x * blockDim.x + threadIdx.x;
    if (i < NN * NW) g_adj[i] = 0u;
}

// -------- scatter edges (symmetric, no self loops, dedup via OR); edge_index is int32 --------
__global__ void build_adj_kernel(const int* __restrict__ ei, int ne) {
    int e = blockIdx.x * blockDim.x + threadIdx.x;
    if (e >= ne) return;
    int s = ei[e];
    int d = ei[ne + e];
    if (s == d) return;
    if ((unsigned)s >= NN || (unsigned)d >= NN) return;
    atomicOr(&g_adj[s * NW + (d >> 5)], 1u << (d & 31));
    atomicOr(&g_adj[d * NW + (s >> 5)], 1u << (s & 31));
}

// -------- deterministic compaction: block prefix-scan, sorted neighbor lists --------
__global__ void compact_kernel() {
    __shared__ int wsum[4];
    int n = blockIdx.x, t = threadIdx.x;
    unsigned bits = g_adj[n * NW + t];
    int c = __popc(bits);
    int lane = t & 31, w = t >> 5;
    int x = c;
#pragma unroll
    for (int o = 1; o < 32; o <<= 1) {
        int y = __shfl_up_sync(0xffffffffu, x, o);
        if (lane >= o) x += y;
    }
    if (lane == 31) wsum[w] = x;
    __syncthreads();
    int woff = 0;
#pragma unroll
    for (int i = 0; i < 4; i++) if (i < w) woff += wsum[i];
    int base = woff + x - c;                // exclusive prefix
    int total = wsum[0] + wsum[1] + wsum[2] + wsum[3];
    while (bits) {
        int b = __ffs(bits) - 1;
        bits &= bits - 1;
        if (base < MAXD) g_nbr[n * MAXD + base] = t * 32 + b;
        base++;
    }
    if (t == 0) g_deg[n] = (total < MAXD) ? total : MAXD;
}

// ======== tf32 wmma GEMM: C[M,Nc] = A[M,K] @ B[Nc,K]^T + bias ========
// BM=128, BN=64, BK=16 (2 wmma k-steps), 256 threads (8 warps, 4x2 warp grid,
// warp tile 32x32 = 2x2 m16n16k8 fragments). Double-buffered smem, tf32 RN
// conversion at smem store. Epilogue via smem staging (union w/ pipe buffers).
// ASEL: 0 = emb, 1 = g_ctx, 2 = g_x;  CSEL: 0 = g_qkv, 1 = g_x, 2 = g_y
#define BM 128
#define BN 64
#define GBK 16
#define BKP 20          // padded K-stride (floats), multiple of 4
#define GNT 256

struct GemmSmem {
    union {
        struct {
            float As[2][BM][BKP];   // 20480 B
            float Bs[2][BN][BKP];   // 10240 B
        } p;
        float stage[8][32][36];     // 36864 B  (per-warp 32x32 output staging, +4 pad)
    };
};

template<int ASEL, int CSEL, bool SELECT>
__global__ __launch_bounds__(GNT) void gemm_kernel(const float* __restrict__ emb,
                                                   const float* __restrict__ B,
                                                   const float* __restrict__ bias,
                                                   int Nc, int K) {
    const float* A = (ASEL == 0) ? emb : (ASEL == 1 ? (const float*)g_ctx : (const float*)g_x);
    float*       C = (CSEL == 0) ? g_qkv : (CSEL == 1 ? g_x : g_y);

    __shared__ GemmSmem sm;

    const int tid = threadIdx.x;
    const int w = tid >> 5, lane = tid & 31;
    const int wy = w >> 1, wx = w & 1;          // warp grid 4x2
    const int row0 = blockIdx.y * BM;
    const int col0 = blockIdx.x * BN;

    // global-load staging: A = 512 float4 (2/thread), B = 256 float4 (1/thread)
    float4 ra[2], rb;
    auto gload = [&](int k0) {
#pragma unroll
        for (int u = 0; u < 2; u++) {
            int i = tid + u * GNT;
            int r = i >> 2, kk = (i & 3) * 4;
            ra[u] = *(const float4*)(A + (size_t)(row0 + r) * K + k0 + kk);
        }
        {
            int r = tid >> 2, kk = (tid & 3) * 4;
            rb = *(const float4*)(B + (size_t)(col0 + r) * K + k0 + kk);
        }
    };
    auto sstore = [&](int buf) {
#pragma unroll
        for (int u = 0; u < 2; u++) {
            int i = tid + u * GNT;
            int r = i >> 2, kk = (i & 3) * 4;
            sm.p.As[buf][r][kk + 0] = wmma::__float_to_tf32(ra[u].x);
            sm.p.As[buf][r][kk + 1] = wmma::__float_to_tf32(ra[u].y);
            sm.p.As[buf][r][kk + 2] = wmma::__float_to_tf32(ra[u].z);
            sm.p.As[buf][r][kk + 3] = wmma::__float_to_tf32(ra[u].w);
        }
        {
            int r = tid >> 2, kk = (tid & 3) * 4;
            sm.p.Bs[buf][r][kk + 0] = wmma::__float_to_tf32(rb.x);
            sm.p.Bs[buf][r][kk + 1] = wmma::__float_to_tf32(rb.y);
            sm.p.Bs[buf][r][kk + 2] = wmma::__float_to_tf32(rb.z);
            sm.p.Bs[buf][r][kk + 3] = wmma::__float_to_tf32(rb.w);
        }
    };

    wmma::fragment<wmma::accumulator, 16, 16, 8, float> cf[2][2];
#pragma unroll
    for (int i = 0; i < 2; i++)
#pragma unroll
        for (int j = 0; j < 2; j++)
            wmma::fill_fragment(cf[i][j], 0.0f);

    gload(0);
    sstore(0);
    __syncthreads();

    const int KT = K / GBK;
    for (int kt = 0; kt < KT; kt++) {
        int buf = kt & 1;
        if (kt + 1 < KT) gload((kt + 1) * GBK);
#pragma unroll
        for (int ks = 0; ks < GBK; ks += 8) {
            wmma::fragment<wmma::matrix_a, 16, 16, 8, wmma::precision::tf32, wmma::row_major> af[2];
            wmma::fragment<wmma::matrix_b, 16, 16, 8, wmma::precision::tf32, wmma::col_major> bf[2];
#pragma unroll
            for (int i = 0; i < 2; i++)
                wmma::load_matrix_sync(af[i], &sm.p.As[buf][wy * 32 + i * 16][ks], BKP);
#pragma unroll
            for (int j = 0; j < 2; j++)
                wmma::load_matrix_sync(bf[j], &sm.p.Bs[buf][wx * 32 + j * 16][ks], BKP);
#pragma unroll
            for (int i = 0; i < 2; i++)
#pragma unroll
                for (int j = 0; j < 2; j++)
                    wmma::mma_sync(cf[i][j], af[i], bf[j], cf[i][j]);
        }
        if (kt + 1 < KT) {
            sstore(buf ^ 1);
            __syncthreads();
        }
    }

    // epilogue: stage accumulators to smem (aliases pipe buffers), add bias, select, store
    __syncthreads();
#pragma unroll
    for (int i = 0; i < 2; i++)
#pragma unroll
        for (int j = 0; j < 2; j++)
            wmma::store_matrix_sync(&sm.stage[w][i * 16][j * 16], cf[i][j], 36, wmma::mem_row_major);
    __syncwarp();

    {
        int r = row0 + wy * 32 + lane;
        bool alt = SELECT && (g_deg[r] == 0);
        int cbase = col0 + wx * 32;
#pragma unroll
        for (int j = 0; j < 8; j++) {
            int cc = cbase + j * 4;
            float4 bv = *(const float4*)(bias + cc);
            float4 v;
            v.x = sm.stage[w][lane][j * 4 + 0] + bv.x;
            v.y = sm.stage[w][lane][j * 4 + 1] + bv.y;
            v.z = sm.stage[w][lane][j * 4 + 2] + bv.z;
            v.w = sm.stage[w][lane][j * 4 + 3] + bv.w;
            if (SELECT && alt) v = *(const float4*)(emb + (size_t)r * DD + cc);
            *(float4*)(C + (size_t)r * Nc + cc) = v;
        }
    }
}

// -------- sparse attention: warp per (node, head), online softmax, 4-way unrolled --------
__global__ void attn_kernel() {
    __shared__ int snbr[MAXD];
    __shared__ int sdeg;
    int n = blockIdx.x, tid = threadIdx.x;
    if (tid == 0) sdeg = g_deg[n];
    __syncthreads();
    int dg = sdeg;
    for (int i = tid; i < dg; i += 256) snbr[i] = g_nbr[(size_t)n * MAXD + i];
    __syncthreads();
    if (dg == 0) {
        g_ctx[(size_t)n * DD + tid] = 0.f;
        return;
    }

    float q = g_qkv[(size_t)n * 768 + tid];   // q occupies [0,256); tid = head*32+lane
    float m = -1e30f, s = 0.f, acc = 0.f;
    const float sc = 0.17677669529663687f;    // 1/sqrt(32)

    for (int i = 0; i < dg; i += 4) {
        int i1 = min(i + 1, dg - 1), i2 = min(i + 2, dg - 1), i3 = min(i + 3, dg - 1);
        const float* b0 = g_qkv + (size_t)snbr[i]  * 768 + 256 + tid;
        const float* b1 = g_qkv + (size_t)snbr[i1] * 768 + 256 + tid;
        const float* b2 = g_qkv + (size_t)snbr[i2] * 768 + 256 + tid;
        const float* b3 = g_qkv + (size_t)snbr[i3] * 768 + 256 + tid;
        float k0 = b0[0], k1 = b1[0], k2 = b2[0], k3 = b3[0];
        float v0 = b0[256], v1 = b1[256], v2 = b2[256], v3 = b3[256];

        float p0 = q * k0, p1 = q * k1, p2 = q * k2, p3 = q * k3;
#pragma unroll
        for (int o = 16; o; o >>= 1) {
            p0 += __shfl_xor_sync(0xffffffffu, p0, o);
            p1 += __shfl_xor_sync(0xffffffffu, p1, o);
            p2 += __shfl_xor_sync(0xffffffffu, p2, o);
            p3 += __shfl_xor_sync(0xffffffffu, p3, o);
        }
        p0 *= sc; p1 *= sc; p2 *= sc; p3 *= sc;
        if (i + 1 >= dg) p1 = -1e30f;
        if (i + 2 >= dg) p2 = -1e30f;
        if (i + 3 >= dg) p3 = -1e30f;

        float mx = fmaxf(fmaxf(fmaxf(p0, p1), fmaxf(p2, p3)), m);
        float f  = __expf(m - mx);
        float e0 = __expf(p0 - mx), e1 = __expf(p1 - mx);
        float e2 = __expf(p2 - mx), e3 = __expf(p3 - mx);
        s   = s * f + e0 + e1 + e2 + e3;
        acc = acc * f + e0 * v0 + e1 * v1 + e2 * v2 + e3 * v3;
        m = mx;
    }
    g_ctx[(size_t)n * DD + tid] = acc / s;
}

// -------- fused LayerNorm + exact GELU --------
__global__ void ln_gelu_kernel(const float* __restrict__ g, const float* __restrict__ beta,
                               float* __restrict__ out) {
    __shared__ float red1[8];
    __shared__ float red2[8];
    int r = blockIdx.x;
    int t = threadIdx.x;
    float v = g_y[(size_t)r * DD + t];

    float x = v, x2 = v * v;
#pragma unroll
    for (int o = 16; o; o >>= 1) {
        x  += __shfl_xor_sync(0xffffffffu, x, o);
        x2 += __shfl_xor_sync(0xffffffffu, x2, o);
    }
    if ((t & 31) == 0) { red1[t >> 5] = x; red2[t >> 5] = x2; }
    __syncthreads();
    float sum = 0.f, ss = 0.f;
#pragma unroll
    for (int i = 0; i < 8; i++) { sum += red1[i]; ss += red2[i]; }
    float mean = sum * (1.f / 256.f);
    float var  = ss * (1.f / 256.f) - mean * mean;

    float yv = (v - mean) * rsqrtf(var + 1e-5f) * g[t] + beta[t];
    out[(size_t)r * DD + t] = 0.5f * yv * (1.f + erff(yv * 0.70710678118654752f));
}

// ------------------------------------------------------------------
extern "C" void kernel_launch(void* const* d_in, const int* in_sizes, int n_in,
                              void* d_out, int out_size) {
    const float* emb   = (const float*)d_in[0];
    const int*   ei    = (const int*)d_in[1];     // int32 (JAX default)
    const float* w_in  = (const float*)d_in[2];
    const float* b_in  = (const float*)d_in[3];
    const float* w_out = (const float*)d_in[4];
    const float* b_out = (const float*)d_in[5];
    const float* w_lin = (const float*)d_in[6];
    const float* b_lin = (const float*)d_in[7];
    const float* ln_g  = (const float*)d_in[8];
    const float* ln_b  = (const float*)d_in[9];
    float* out = (float*)d_out;

    const int ne = in_sizes[1] / 2;

    // 1. adjacency
    zero_adj_kernel<<<(NN * NW + 255) / 256, 256>>>();
    build_adj_kernel<<<(ne + 255) / 256, 256>>>(ei, ne);
    compact_kernel<<<NN, NW>>>();

    // 2. qkv = emb @ W_in^T + b_in   [4096, 768]
    gemm_kernel<0, 0, false><<<dim3(768 / BN, NN / BM), GNT>>>(emb, w_in, b_in, 768, DD);

    // 3. sparse masked attention -> ctx [4096, 256]
    attn_kernel<<<NN, 256>>>();

    // 4. x = has_nb ? ctx @ W_out^T + b_out : emb
    gemm_kernel<1, 1, true><<<dim3(DD / BN, NN / BM), GNT>>>(emb, w_out, b_out, DD, DD);

    // 5. y = x @ W_lin^T + b_lin
    gemm_kernel<2, 2, false><<<dim3(DD / BN, NN / BM), GNT>>>(emb, w_lin, b_lin, DD, DD);

    // 6. LayerNorm + exact GELU -> out
    ln_gelu_kernel<<<NN, 256>>>(ln_g, ln_b, out);
}